// round 10
// baseline (speedup 1.0000x reference)
#include <cuda_runtime.h>

// Problem constants (fixed by the reference setup_inputs)
#define BB 64
#define SS 2048
#define DD 768
#define DD4 192          // DD / 4 (float4)
#define POOL 32
#define LL 8
#define TOPK 4
#define PROMPT_ROWS 41   // L + TOPK*L + 1
#define ROWS_OUT 2089    // PROMPT_ROWS + SS
#define SCHUNK 64
#define NCHUNK 32        // SS / SCHUNK -> grid 2048 (measured-best config)
#define NGRP 4           // chunk groups in k2 (8 chunks each)
#define EPSV 1e-12f

// Scratch (no allocations allowed in kernel_launch)
__device__ float g_partial[NCHUNK * BB * DD];   // ~6.3 MB
__device__ float g_dotp[NGRP * BB * POOL];      // 32 KB partial key-dots

// ---------------------------------------------------------------------------
// Kernel 1: stream-copy x -> out tail + per-(chunk,b,d) partial sums.
// EXACT measured-best stream config. PDL trigger at end.
// grid = (NCHUNK, BB) = 2048 blocks, block = 192 threads.
// ---------------------------------------------------------------------------
__global__ void k_copy_reduce(const float4* __restrict__ x,
                              float4* __restrict__ out) {
    const int b     = blockIdx.y;
    const int chunk = blockIdx.x;
    const int d4    = threadIdx.x;                   // 0..191

    const float4* xp = x   + ((size_t)b * SS + (size_t)chunk * SCHUNK) * DD4 + d4;
    float4*       op = out + ((size_t)b * ROWS_OUT + PROMPT_ROWS
                              + (size_t)chunk * SCHUNK) * DD4 + d4;

    float4 acc = make_float4(0.f, 0.f, 0.f, 0.f);
    #pragma unroll 8
    for (int s = 0; s < SCHUNK; s++) {
        float4 v = xp[(size_t)s * DD4];
        op[(size_t)s * DD4] = v;
        acc.x += v.x; acc.y += v.y; acc.z += v.z; acc.w += v.w;
    }
    ((float4*)g_partial)[((size_t)chunk * BB + b) * DD4 + d4] = acc;

#if __CUDA_ARCH__ >= 900
    cudaTriggerProgrammaticLaunchCompletion();
#endif
}

// ---------------------------------------------------------------------------
// Kernel 2 (PDL): grid (NGRP, BB) = 256 blocks, 384 threads. Each block
// reduces 8 chunks of batch b's partials and dots the partial-q against all
// 32 keys (dot is linear in q => partial dots sum to the full dot).
// Pre-sync prologue: group 0 writes the 9 topk-independent prompt rows.
// ---------------------------------------------------------------------------
__global__ void k_reduce_dot(const float* __restrict__ keys,
                             const float4* __restrict__ gp,
                             const float4* __restrict__ cls,
                             const int* __restrict__ task_id,
                             float4* __restrict__ out) {
    __shared__ float4 part[2 * DD4];   // 6 KB
    __shared__ float  q_s[DD];         // 3 KB

    const int g = blockIdx.x;          // 0..3
    const int b = blockIdx.y;
    const int t = threadIdx.x;         // 0..383
    const int w = t >> 5, lane = t & 31;

    // Prologue (independent of k1's output region): static prompt rows
    if (g == 0) {
        const int task = task_id[0];
        float4* ob = out + (size_t)b * ROWS_OUT * DD4;
        for (int idx = t; idx < 9 * DD4; idx += 384) {
            const int r  = idx / DD4;          // 0..8
            const int d4 = idx - r * DD4;
            if (r < LL)
                ob[(size_t)r * DD4 + d4] = gp[((size_t)task * LL + r) * DD4 + d4];
            else
                ob[(size_t)(PROMPT_ROWS - 1) * DD4 + d4] = cls[d4];
        }
    }

#if __CUDA_ARCH__ >= 900
    cudaGridDependencySynchronize();
#endif

    // Reduce 8 chunks: (cg in 0..1) x (d4 in 0..191), 4 float4 loads each
    const int cg = t / DD4;            // 0..1
    const int d4 = t - cg * DD4;       // 0..191
    const float4* base = (const float4*)g_partial
                       + ((size_t)(g * 8 + cg * 4) * BB + b) * DD4 + d4;
    float4 acc = make_float4(0.f, 0.f, 0.f, 0.f);
    #pragma unroll
    for (int c = 0; c < 4; c++) {
        const float4 v = base[(size_t)c * BB * DD4];
        acc.x += v.x; acc.y += v.y; acc.z += v.z; acc.w += v.w;
    }
    part[cg * DD4 + d4] = acc;
    __syncthreads();
    if (t < DD4) {
        const float4 a0 = part[t], a1 = part[DD4 + t];
        float4 s;
        s.x = a0.x + a1.x; s.y = a0.y + a1.y;
        s.z = a0.z + a1.z; s.w = a0.w + a1.w;
        ((float4*)q_s)[t] = s;
    }
    __syncthreads();

    // Dot partial-q vs 32 keys: 12 warps, pools p = w + 12*i
    #pragma unroll
    for (int i = 0; i < 3; i++) {
        const int p = w + 12 * i;
        if (p < POOL) {
            float aqk = 0.f;
            #pragma unroll
            for (int d = lane; d < DD; d += 32)
                aqk += q_s[d] * keys[(size_t)p * DD + d];
            #pragma unroll
            for (int o = 16; o > 0; o >>= 1)
                aqk += __shfl_xor_sync(0xffffffffu, aqk, o);
            if (lane == 0) g_dotp[((size_t)g * BB + b) * POOL + p] = aqk;
        }
    }

#if __CUDA_ARCH__ >= 900
    cudaTriggerProgrammaticLaunchCompletion();
#endif
}

// ---------------------------------------------------------------------------
// Kernel 3 (PDL): grid BB, 1024 threads. Pre-sync: key norms + ep prefetch.
// Post-sync: combine 4 partial dots (fixed order), sims (q-norm dropped: a
// positive per-batch factor cannot change ordering), warp-argmax top-4,
// write the 32 e-prompt rows.
// ---------------------------------------------------------------------------
__global__ void k_topk_write(const float* __restrict__ keys,
                             const float4* __restrict__ ep,
                             float4* __restrict__ out) {
    __shared__ float kk_s[POOL];
    __shared__ float sims[POOL];
    __shared__ int   topidx[TOPK];

    const int b = blockIdx.x;
    const int t = threadIdx.x;
    const int w = t >> 5, lane = t & 31;
    float4* ob = out + (size_t)b * ROWS_OUT * DD4;

    // Prologue: key squared norms (warps 0-7, 4 pools each) + ep L2 warm
    if (w < 8) {
        #pragma unroll
        for (int pp = 0; pp < 4; pp++) {
            const int p = w * 4 + pp;
            float a = 0.f;
            #pragma unroll
            for (int d = lane; d < DD; d += 32) {
                const float k = keys[(size_t)p * DD + d];
                a += k * k;
            }
            #pragma unroll
            for (int o = 16; o > 0; o >>= 1)
                a += __shfl_xor_sync(0xffffffffu, a, o);
            if (lane == 0) kk_s[p] = a;
        }
    }
    if (t >= 256 && t < 352) {
        const char* p = (const char*)ep + (size_t)b * 12288
                      + (size_t)(t - 256) * 128;
        asm volatile("prefetch.global.L2 [%0];" :: "l"(p));
    }

#if __CUDA_ARCH__ >= 900
    cudaGridDependencySynchronize();
#endif
    __syncthreads();                   // kk_s visible to all

    // Combine partial dots in fixed order -> sims
    if (t < POOL) {
        const float d0 = g_dotp[(0 * BB + b) * POOL + t];
        const float d1 = g_dotp[(1 * BB + b) * POOL + t];
        const float d2 = g_dotp[(2 * BB + b) * POOL + t];
        const float d3 = g_dotp[(3 * BB + b) * POOL + t];
        sims[t] = (((d0 + d1) + d2) + d3) * rsqrtf(kk_s[t] + EPSV);
    }
    __syncthreads();

    // Warp 0: top-4 via warp argmax (desc, lowest index on tie)
    if (w == 0) {
        float v = sims[lane];
        #pragma unroll
        for (int k = 0; k < TOPK; k++) {
            float bv = v; int bi = lane;
            #pragma unroll
            for (int o = 16; o > 0; o >>= 1) {
                const float ov = __shfl_xor_sync(0xffffffffu, bv, o);
                const int   oi = __shfl_xor_sync(0xffffffffu, bi, o);
                if (ov > bv || (ov == bv && oi < bi)) { bv = ov; bi = oi; }
            }
            if (lane == 0) topidx[k] = bi;
            if (lane == bi) v = -3.402823e38f;   // remove winner
        }
    }
    __syncthreads();

    // Write the 32 e-prompt rows (rows 8..39), 6144 float4 (~6/thread)
    for (int idx = t; idx < POOL * DD4; idx += 1024) {
        const int rr = idx / DD4;          // 0..31
        const int d4 = idx - rr * DD4;
        const float4* src = ep + ((size_t)topidx[rr >> 3] * LL + (rr & 7)) * DD4;
        ob[(size_t)(LL + rr) * DD4 + d4] = src[d4];
    }
}

// ---------------------------------------------------------------------------
extern "C" void kernel_launch(void* const* d_in, const int* in_sizes, int n_in,
                              void* d_out, int out_size) {
    const float4* x   = (const float4*)d_in[0];   // [64,2048,768]
    const float4* gp  = (const float4*)d_in[1];   // [10,8,768]
    const float4* ep  = (const float4*)d_in[2];   // [32,8,768]
    const float*  key = (const float*) d_in[3];   // [32,768]
    const float4* cls = (const float4*)d_in[4];   // [1,1,768]
    const int*    tid = (const int*)   d_in[5];   // scalar task_id
    float4* out = (float4*)d_out;

    k_copy_reduce<<<dim3(NCHUNK, BB), 192>>>(x, out);

    cudaLaunchAttribute attr[1];
    attr[0].id = cudaLaunchAttributeProgrammaticStreamSerialization;
    attr[0].val.programmaticStreamSerializationAllowed = 1;

    cudaLaunchConfig_t cfg2 = {};
    cfg2.gridDim  = dim3(NGRP, BB);
    cfg2.blockDim = dim3(384);
    cfg2.stream   = 0;
    cfg2.attrs    = attr;
    cfg2.numAttrs = 1;
    cudaLaunchKernelEx(&cfg2, k_reduce_dot, key, gp, cls, tid, out);

    cudaLaunchConfig_t cfg3 = {};
    cfg3.gridDim  = dim3(BB);
    cfg3.blockDim = dim3(1024);
    cfg3.stream   = 0;
    cfg3.attrs    = attr;
    cfg3.numAttrs = 1;
    cudaLaunchKernelEx(&cfg3, k_topk_write, key, ep, out);
}

// round 11
// speedup vs baseline: 1.0413x; 1.0413x over previous
#include <cuda_runtime.h>
#include <cooperative_groups.h>

namespace cg = cooperative_groups;

// Problem constants (fixed by the reference setup_inputs)
#define BB 64
#define SS 2048
#define DD 768
#define DD4 192          // DD / 4 (float4)
#define POOL 32
#define LL 8
#define TOPK 4
#define PROMPT_ROWS 41   // L + TOPK*L + 1
#define ROWS_OUT 2089    // PROMPT_ROWS + SS
#define SCHUNK 64
#define NCHUNK 32        // SS / SCHUNK -> grid 2048 (measured-best config)
#define CRANKS 4         // cluster size (d-quarters)
#define DQ 192           // dims per rank
#define DQ4 48           // float4 per rank
#define EPSV 1e-12f

// Scratch (no allocations allowed in kernel_launch)
__device__ float g_partial[NCHUNK * BB * DD];   // ~6.3 MB

// ---------------------------------------------------------------------------
// Kernel 1: stream-copy x -> out tail + per-(chunk,b,d) partial sums.
// EXACT measured-best stream config (119.4us @ ~80% DRAM). PDL trigger.
// grid = (NCHUNK, BB) = 2048 blocks, block = 192 threads.
// ---------------------------------------------------------------------------
__global__ void k_copy_reduce(const float4* __restrict__ x,
                              float4* __restrict__ out) {
    const int b     = blockIdx.y;
    const int chunk = blockIdx.x;
    const int d4    = threadIdx.x;                   // 0..191

    const float4* xp = x   + ((size_t)b * SS + (size_t)chunk * SCHUNK) * DD4 + d4;
    float4*       op = out + ((size_t)b * ROWS_OUT + PROMPT_ROWS
                              + (size_t)chunk * SCHUNK) * DD4 + d4;

    float4 acc = make_float4(0.f, 0.f, 0.f, 0.f);
    #pragma unroll 8
    for (int s = 0; s < SCHUNK; s++) {
        float4 v = xp[(size_t)s * DD4];
        op[(size_t)s * DD4] = v;
        acc.x += v.x; acc.y += v.y; acc.z += v.z; acc.w += v.w;
    }
    ((float4*)g_partial)[((size_t)chunk * BB + b) * DD4 + d4] = acc;

#if __CUDA_ARCH__ >= 900
    cudaTriggerProgrammaticLaunchCompletion();
#endif
}

// ---------------------------------------------------------------------------
// Kernel 2 (PDL, 4-CTA cluster per batch): rank r owns d-quarter
// [192r,192r+192). Pre-sync prologue: key-norm quarter, static prompt rows,
// ep prefetch. Post-sync: quarter reduce, quarter key-dots (linear in d),
// DSMEM all-gather of 32+32 partials, deterministic combine, sims (q-norm
// dropped: positive per-batch factor cannot change ordering), warp-argmax
// top-4 (redundant per CTA), write this rank's quarter of the 41 rows.
// grid = (CRANKS, BB) = 256 blocks, block = 256 threads.
// ---------------------------------------------------------------------------
__global__ void __cluster_dims__(CRANKS, 1, 1)
k_topk_prompts(const float* __restrict__ keys,
               const float4* __restrict__ gp,
               const float4* __restrict__ ep,
               const float4* __restrict__ cls,
               const int* __restrict__ task_id,
               float4* __restrict__ out) {
    __shared__ float4 part[4 * DQ4];          // 3 KB
    __shared__ float  q_s[DQ];                // this rank's quarter of q
    __shared__ float  dot_loc[POOL];          // this rank's partial dots
    __shared__ float  kk_loc[POOL];           // this rank's partial key norms
    __shared__ float  dot_x[CRANKS * POOL];   // gathered from all ranks
    __shared__ float  kk_x[CRANKS * POOL];
    __shared__ float  sims[POOL];
    __shared__ int    topidx[TOPK];

    cg::cluster_group cluster = cg::this_cluster();
    const int r = blockIdx.x;          // cluster rank 0..3
    const int b = blockIdx.y;
    const int t = threadIdx.x;         // 0..255
    const int w = t >> 5, lane = t & 31;
    float4* ob = out + (size_t)b * ROWS_OUT * DD4;

    // ---------------- prologue (independent of kernel 1) ----------------
    // (a) key-norm partial over this rank's d-quarter: 8 warps x 4 pools
    {
        #pragma unroll
        for (int pp = 0; pp < 4; pp++) {
            const int p = w * 4 + pp;
            float a = 0.f;
            #pragma unroll
            for (int d = lane; d < DQ; d += 32) {
                const float k = keys[(size_t)p * DD + r * DQ + d];
                a += k * k;
            }
            #pragma unroll
            for (int o = 16; o > 0; o >>= 1)
                a += __shfl_xor_sync(0xffffffffu, a, o);
            if (lane == 0) kk_loc[p] = a;
        }
    }
    // (b) static prompt rows 0..7 (g_prompts[task]) and 40 (cls),
    //     split across ranks: 1728 float4 total, 432 per rank
    {
        const int task = task_id[0];
        for (int idx = t; idx < 432; idx += 256) {
            const int gidx = r * 432 + idx;
            const int row  = gidx / DD4;       // 0..8
            const int d4   = gidx - row * DD4;
            if (row < LL)
                ob[(size_t)row * DD4 + d4] = gp[((size_t)task * LL + row) * DD4 + d4];
            else
                ob[(size_t)(PROMPT_ROWS - 1) * DD4 + d4] = cls[d4];
        }
    }
    // (c) warm e_prompts into L2 (768 KB / 256 CTAs = 3 KB each)
    if (t < 24) {
        const char* p = (const char*)ep + ((size_t)b * CRANKS + r) * 3072
                      + (size_t)t * 128;
        asm volatile("prefetch.global.L2 [%0];" :: "l"(p));
    }

    // ---------------- wait for kernel 1's partials ----------------
#if __CUDA_ARCH__ >= 900
    cudaGridDependencySynchronize();
#endif

    // Phase A: reduce 32 chunks over this rank's 48 float4 columns.
    // t<192: cgp = chunk-group (8 chunks), d4l = local float4 column.
    if (t < 192) {
        const int cgp = t / DQ4;       // 0..3
        const int d4l = t - cgp * DQ4; // 0..47
        const float4* base = (const float4*)g_partial
                           + ((size_t)(cgp * 8) * BB + b) * DD4 + r * DQ4 + d4l;
        float4 acc = make_float4(0.f, 0.f, 0.f, 0.f);
        #pragma unroll
        for (int c = 0; c < 8; c++) {
            const float4 v = base[(size_t)c * BB * DD4];
            acc.x += v.x; acc.y += v.y; acc.z += v.z; acc.w += v.w;
        }
        part[cgp * DQ4 + d4l] = acc;
    }
    __syncthreads();
    if (t < DQ4) {
        const float4 a0 = part[t], a1 = part[DQ4 + t],
                     a2 = part[2 * DQ4 + t], a3 = part[3 * DQ4 + t];
        float4 s;
        s.x = (a0.x + a1.x) + (a2.x + a3.x);
        s.y = (a0.y + a1.y) + (a2.y + a3.y);
        s.z = (a0.z + a1.z) + (a2.z + a3.z);
        s.w = (a0.w + a1.w) + (a2.w + a3.w);
        ((float4*)q_s)[t] = s;
    }
    __syncthreads();

    // Phase B: partial dots over this quarter: 8 warps x 4 pools
    {
        #pragma unroll
        for (int pp = 0; pp < 4; pp++) {
            const int p = w * 4 + pp;
            float aqk = 0.f;
            #pragma unroll
            for (int d = lane; d < DQ; d += 32)
                aqk += q_s[d] * keys[(size_t)p * DD + r * DQ + d];
            #pragma unroll
            for (int o = 16; o > 0; o >>= 1)
                aqk += __shfl_xor_sync(0xffffffffu, aqk, o);
            if (lane == 0) dot_loc[p] = aqk;
        }
    }
    __syncthreads();

    // DSMEM all-gather: write this rank's 32+32 partials into every CTA
    if (t < POOL) {
        #pragma unroll
        for (int dr = 0; dr < CRANKS; dr++) {
            float* rdot = (float*)cluster.map_shared_rank(dot_x, dr);
            float* rkk  = (float*)cluster.map_shared_rank(kk_x,  dr);
            rdot[r * POOL + t] = dot_loc[t];
            rkk [r * POOL + t] = kk_loc[t];
        }
    }
    cluster.sync();

    // Combine in fixed rank order -> sims
    if (t < POOL) {
        const float dsum = ((dot_x[t] + dot_x[POOL + t])
                          + dot_x[2 * POOL + t]) + dot_x[3 * POOL + t];
        const float ksum = ((kk_x[t] + kk_x[POOL + t])
                          + kk_x[2 * POOL + t]) + kk_x[3 * POOL + t];
        sims[t] = dsum * rsqrtf(ksum + EPSV);
    }
    __syncthreads();

    // Warp 0: top-4 via warp argmax (desc, lowest index on tie)
    if (w == 0) {
        float v = sims[lane];
        #pragma unroll
        for (int k = 0; k < TOPK; k++) {
            float bv = v; int bi = lane;
            #pragma unroll
            for (int o = 16; o > 0; o >>= 1) {
                const float ov = __shfl_xor_sync(0xffffffffu, bv, o);
                const int   oi = __shfl_xor_sync(0xffffffffu, bi, o);
                if (ov > bv || (ov == bv && oi < bi)) { bv = ov; bi = oi; }
            }
            if (lane == 0) topidx[k] = bi;
            if (lane == bi) v = -3.402823e38f;   // remove winner
        }
    }
    __syncthreads();

    // Write e-prompt rows 8..39: 6144 float4 total, 1536 per rank
    for (int idx = t; idx < 1536; idx += 256) {
        const int gidx = r * 1536 + idx;
        const int rr   = gidx / DD4;       // 0..31
        const int d4   = gidx - rr * DD4;
        const float4* src = ep + ((size_t)topidx[rr >> 3] * LL + (rr & 7)) * DD4;
        ob[(size_t)(LL + rr) * DD4 + d4] = src[d4];
    }
    // No trailing cluster.sync needed for correctness of global writes;
    // but DSMEM safety requires no CTA exits while peers may still write.
    // All DSMEM writes happened before cluster.sync() above, so we're safe.
}

// ---------------------------------------------------------------------------
extern "C" void kernel_launch(void* const* d_in, const int* in_sizes, int n_in,
                              void* d_out, int out_size) {
    const float4* x   = (const float4*)d_in[0];   // [64,2048,768]
    const float4* gp  = (const float4*)d_in[1];   // [10,8,768]
    const float4* ep  = (const float4*)d_in[2];   // [32,8,768]
    const float*  key = (const float*) d_in[3];   // [32,768]
    const float4* cls = (const float4*)d_in[4];   // [1,1,768]
    const int*    tid = (const int*)   d_in[5];   // scalar task_id
    float4* out = (float4*)d_out;

    k_copy_reduce<<<dim3(NCHUNK, BB), 192>>>(x, out);

    // Dependent cluster launch with programmatic stream serialization (PDL)
    cudaLaunchConfig_t cfg = {};
    cfg.gridDim  = dim3(CRANKS, BB);
    cfg.blockDim = dim3(256);
    cfg.stream   = 0;
    cudaLaunchAttribute attr[1];
    attr[0].id = cudaLaunchAttributeProgrammaticStreamSerialization;
    attr[0].val.programmaticStreamSerializationAllowed = 1;
    cfg.attrs = attr;
    cfg.numAttrs = 1;
    cudaLaunchKernelEx(&cfg, k_topk_prompts, key, gp, ep, cls, tid, out);
}